// round 4
// baseline (speedup 1.0000x reference)
#include <cuda_runtime.h>

// reblurWithKernel: out[c,h,w] = sum_{t=0..8} img[c, clamp(h+t/3-1), clamp(w+t%3-1)] * K[t,h,w]
// img [1,3,1024,1024] f32, K [9,1024,1024] f32, out [1,3,1024,1024] f32.
// Pure HBM-bound (36MB K + 12MB img + 12MB out). Strategy: one thread = 4 pixels x 3 channels;
// ALL 36 loads front-batched into registers (max MLP), then FMAs. K stream uses evict-first
// (__ldcs) so L2 keeps the vertically-reused image lines; output stored streaming (__stcs).

#define H 1024
#define W 1024
#define HW (H * W)

__global__ __launch_bounds__(256, 2)
void reblur_kernel(const float* __restrict__ img,
                   const float* __restrict__ ker,
                   float* __restrict__ out)
{
    const int idx = blockIdx.x * blockDim.x + threadIdx.x;   // one per 4-pixel group
    const int w4 = idx & (W / 4 - 1);                        // 0..255
    const int h  = idx >> 8;                                 // 0..1023
    const int w0 = w4 << 2;

    const int hm = (h > 0)     ? h - 1 : 0;
    const int hp = (h < H - 1) ? h + 1 : H - 1;
    const int wl = (w0 > 0) ? w0 - 1 : 0;          // left halo (clamped)
    const int wr = (w0 + 4 < W) ? w0 + 4 : W - 1;  // right halo (clamped)
    const int rows_idx[3] = {hm, h, hp};

    // ---- Front-batch ALL loads -------------------------------------------
    // 9 per-pixel kernel taps (vectorized over 4 pixels), streaming loads.
    float4 k[9];
    const float4* kp = reinterpret_cast<const float4*>(ker + h * W + w0);
    #pragma unroll
    for (int t = 0; t < 9; t++)
        k[t] = __ldcs(kp + t * (HW / 4));

    // 3 channels x 3 rows: mid float4 + left/right halo scalars.
    float4 mid[3][3];
    float  lh[3][3], rh[3][3];
    #pragma unroll
    for (int c = 0; c < 3; c++) {
        #pragma unroll
        for (int r = 0; r < 3; r++) {
            const float* p = img + c * HW + rows_idx[r] * W;
            mid[c][r] = *reinterpret_cast<const float4*>(p + w0);
            lh[c][r]  = p[wl];
            rh[c][r]  = p[wr];
        }
    }

    // ---- Compute ----------------------------------------------------------
    #pragma unroll
    for (int c = 0; c < 3; c++) {
        float acc0 = 0.f, acc1 = 0.f, acc2 = 0.f, acc3 = 0.f;
        #pragma unroll
        for (int r = 0; r < 3; r++) {
            const float v0 = lh[c][r];
            const float v1 = mid[c][r].x;
            const float v2 = mid[c][r].y;
            const float v3 = mid[c][r].z;
            const float v4 = mid[c][r].w;
            const float v5 = rh[c][r];

            float4 kv;
            kv = k[r * 3 + 0];
            acc0 = fmaf(v0, kv.x, acc0);
            acc1 = fmaf(v1, kv.y, acc1);
            acc2 = fmaf(v2, kv.z, acc2);
            acc3 = fmaf(v3, kv.w, acc3);
            kv = k[r * 3 + 1];
            acc0 = fmaf(v1, kv.x, acc0);
            acc1 = fmaf(v2, kv.y, acc1);
            acc2 = fmaf(v3, kv.z, acc2);
            acc3 = fmaf(v4, kv.w, acc3);
            kv = k[r * 3 + 2];
            acc0 = fmaf(v2, kv.x, acc0);
            acc1 = fmaf(v3, kv.y, acc1);
            acc2 = fmaf(v4, kv.z, acc2);
            acc3 = fmaf(v5, kv.w, acc3);
        }
        float4 o; o.x = acc0; o.y = acc1; o.z = acc2; o.w = acc3;
        __stcs(reinterpret_cast<float4*>(out + c * HW + h * W + w0), o);
    }
}

extern "C" void kernel_launch(void* const* d_in, const int* in_sizes, int n_in,
                              void* d_out, int out_size)
{
    const float* img = (const float*)d_in[0];   // [1,3,1024,1024]
    const float* ker = (const float*)d_in[1];   // [9,1024,1024]
    float* out = (float*)d_out;                 // [1,3,1024,1024]

    const int groups = H * (W / 4);             // 262144 thread work-items
    reblur_kernel<<<groups / 256, 256>>>(img, ker, out);
}

// round 5
// speedup vs baseline: 1.2050x; 1.2050x over previous
#include <cuda_runtime.h>

// reblurWithKernel: out[c,h,w] = sum_{t} img[c, clamp(h+t/3-1), clamp(w+t%3-1)] * K[t,h,w]
// img [1,3,1024,1024] f32, K [9,1024,1024] f32, out same as img.
//
// Bottleneck (R4 analysis): L1tex wavefront throughput (~1 wf/cyc/SM). Halo scalar
// loads at 16B lane stride cost 4 wavefronts per LDG for 32 useful bytes. Fix:
// warp-shuffle halos from neighbor lanes' float4; only lanes 0/31 issue a real
// (predicated, 1-wavefront) boundary load. Index clamping handles image edges:
// at w0==0, p[max(w0-1,0)] == mid.x (replication padding), same on the right.

#define H 1024
#define W 1024
#define HW (H * W)

__global__ __launch_bounds__(256)
void reblur_kernel(const float* __restrict__ img,
                   const float* __restrict__ ker,
                   float* __restrict__ out)
{
    const int idx  = blockIdx.x * 256 + threadIdx.x;  // one per 4-pixel group
    const int w4   = idx & (W / 4 - 1);               // 0..255
    const int h    = idx >> 8;                        // 0..1023
    const int w0   = w4 << 2;
    const int lane = threadIdx.x & 31;

    const int hm = (h > 0)     ? h - 1 : 0;
    const int hp = (h < H - 1) ? h + 1 : H - 1;
    const int rows[3] = {hm, h, hp};
    const int wl = (w0 > 0)     ? w0 - 1 : 0;      // clamped: ==w0 at left edge
    const int wr = (w0 + 4 < W) ? w0 + 4 : W - 1;  // clamped: ==w0+3 at right edge

    // 9 per-pixel kernel taps, vectorized over the 4 pixels (read-once stream).
    float4 k[9];
    const float* kp = ker + h * W + w0;
    #pragma unroll
    for (int t = 0; t < 9; t++)
        k[t] = *reinterpret_cast<const float4*>(kp + t * HW);

    #pragma unroll
    for (int c = 0; c < 3; c++) {
        const float* base = img + c * HW;

        // 3 rows of 4 pixels each (coalesced float4).
        float4 m[3];
        #pragma unroll
        for (int r = 0; r < 3; r++)
            m[r] = *reinterpret_cast<const float4*>(base + rows[r] * W + w0);

        // Warp-boundary halos: predicated single-lane loads (1 wavefront each).
        float lv[3], rv[3];
        #pragma unroll
        for (int r = 0; r < 3; r++) {
            lv[r] = (lane == 0)  ? base[rows[r] * W + wl] : 0.f;
            rv[r] = (lane == 31) ? base[rows[r] * W + wr] : 0.f;
        }

        // Interior halos via shuffle from neighbor lanes (warp = 128 contiguous px).
        #pragma unroll
        for (int r = 0; r < 3; r++) {
            float sl = __shfl_up_sync  (0xffffffffu, m[r].w, 1);
            float sr = __shfl_down_sync(0xffffffffu, m[r].x, 1);
            if (lane != 0)  lv[r] = sl;
            if (lane != 31) rv[r] = sr;
        }

        float acc0 = 0.f, acc1 = 0.f, acc2 = 0.f, acc3 = 0.f;
        #pragma unroll
        for (int r = 0; r < 3; r++) {
            const float v0 = lv[r];
            const float v1 = m[r].x;
            const float v2 = m[r].y;
            const float v3 = m[r].z;
            const float v4 = m[r].w;
            const float v5 = rv[r];

            float4 kv;
            kv = k[r * 3 + 0];
            acc0 = fmaf(v0, kv.x, acc0);
            acc1 = fmaf(v1, kv.y, acc1);
            acc2 = fmaf(v2, kv.z, acc2);
            acc3 = fmaf(v3, kv.w, acc3);
            kv = k[r * 3 + 1];
            acc0 = fmaf(v1, kv.x, acc0);
            acc1 = fmaf(v2, kv.y, acc1);
            acc2 = fmaf(v3, kv.z, acc2);
            acc3 = fmaf(v4, kv.w, acc3);
            kv = k[r * 3 + 2];
            acc0 = fmaf(v2, kv.x, acc0);
            acc1 = fmaf(v3, kv.y, acc1);
            acc2 = fmaf(v4, kv.z, acc2);
            acc3 = fmaf(v5, kv.w, acc3);
        }

        float4 o; o.x = acc0; o.y = acc1; o.z = acc2; o.w = acc3;
        *reinterpret_cast<float4*>(out + c * HW + h * W + w0) = o;
    }
}

extern "C" void kernel_launch(void* const* d_in, const int* in_sizes, int n_in,
                              void* d_out, int out_size)
{
    const float* img = (const float*)d_in[0];   // [1,3,1024,1024]
    const float* ker = (const float*)d_in[1];   // [9,1024,1024]
    float* out = (float*)d_out;                 // [1,3,1024,1024]

    const int groups = H * (W / 4);             // 262144 work-items
    reblur_kernel<<<groups / 256, 256>>>(img, ker, out);
}

// round 6
// speedup vs baseline: 1.4345x; 1.1905x over previous
#include <cuda_runtime.h>

// Per-pixel 3x3 conv, kernels shared across channels, edge-replication pad.
// img [1,3,1024,1024] f32, K [9,1024,1024] f32, out [1,3,1024,1024] f32.
//
// R6: register row-rolling. Each thread computes a 4-px column x 4 output rows
// x 3 channels. A 3-row image window (float4 + halo scalars) rolls in registers,
// so each image row is loaded from memory once per 3 uses (18 B/px instead of
// 36 B/px). K taps stream once (irreducible 36 B/px). Halos via warp shuffle;
// only lanes 0/31 issue predicated 1-wavefront boundary loads.

#define H 1024
#define W 1024
#define HW (H * W)
#define RPT 4              // output rows per thread

__global__ __launch_bounds__(128)
void reblur_kernel(const float* __restrict__ img,
                   const float* __restrict__ ker,
                   float* __restrict__ out)
{
    const int bid  = blockIdx.x;           // 512 blocks
    const int tid  = threadIdx.x;          // 128 threads -> 512 px of one row
    const int lane = tid & 31;

    const int w0 = (bid & 1) * 512 + tid * 4;   // 4-px column start
    const int h0 = (bid >> 1) * RPT;            // first output row

    const int  wl  = (w0 > 0)     ? w0 - 1 : 0;      // clamped left halo col
    const int  wr  = (w0 + 4 < W) ? w0 + 4 : W - 1;  // clamped right halo col
    const bool isL = (lane == 0);
    const bool isR = (lane == 31);

    float4 m [3][3];           // [channel][window row: h-1,h,h+1]
    float  lv[3][3], rv[3][3]; // rolled boundary halos (valid in lanes 0/31)

    // ---- init window: rows h0-1 (clamped), h0, h0+1 ----
    #pragma unroll
    for (int j = 0; j < 3; j++) {
        int row = h0 - 1 + j;
        row = (row < 0) ? 0 : row;
        #pragma unroll
        for (int c = 0; c < 3; c++) {
            const float* p = img + c * HW + row * W;
            m[c][j]  = *reinterpret_cast<const float4*>(p + w0);
            lv[c][j] = isL ? p[wl] : 0.f;
            rv[c][j] = isR ? p[wr] : 0.f;
        }
    }

    #pragma unroll
    for (int r = 0; r < RPT; r++) {
        const int h = h0 + r;

        // 9 per-pixel kernel taps for this output row (read-once stream).
        float4 k[9];
        const float* kp = ker + h * W + w0;
        #pragma unroll
        for (int t = 0; t < 9; t++)
            k[t] = *reinterpret_cast<const float4*>(kp + t * HW);

        #pragma unroll
        for (int c = 0; c < 3; c++) {
            float acc0 = 0.f, acc1 = 0.f, acc2 = 0.f, acc3 = 0.f;
            #pragma unroll
            for (int j = 0; j < 3; j++) {
                const float sl = __shfl_up_sync  (0xffffffffu, m[c][j].w, 1);
                const float sr = __shfl_down_sync(0xffffffffu, m[c][j].x, 1);
                const float v0 = isL ? lv[c][j] : sl;
                const float v5 = isR ? rv[c][j] : sr;
                const float v1 = m[c][j].x;
                const float v2 = m[c][j].y;
                const float v3 = m[c][j].z;
                const float v4 = m[c][j].w;

                float4 kv;
                kv = k[j * 3 + 0];
                acc0 = fmaf(v0, kv.x, acc0);
                acc1 = fmaf(v1, kv.y, acc1);
                acc2 = fmaf(v2, kv.z, acc2);
                acc3 = fmaf(v3, kv.w, acc3);
                kv = k[j * 3 + 1];
                acc0 = fmaf(v1, kv.x, acc0);
                acc1 = fmaf(v2, kv.y, acc1);
                acc2 = fmaf(v3, kv.z, acc2);
                acc3 = fmaf(v4, kv.w, acc3);
                kv = k[j * 3 + 2];
                acc0 = fmaf(v2, kv.x, acc0);
                acc1 = fmaf(v3, kv.y, acc1);
                acc2 = fmaf(v4, kv.z, acc2);
                acc3 = fmaf(v5, kv.w, acc3);
            }
            float4 o; o.x = acc0; o.y = acc1; o.z = acc2; o.w = acc3;
            *reinterpret_cast<float4*>(out + c * HW + h * W + w0) = o;
        }

        // ---- roll window: shift up, load row h+2 (clamped) ----
        if (r < RPT - 1) {
            int nrow = h + 2;
            nrow = (nrow > H - 1) ? H - 1 : nrow;
            #pragma unroll
            for (int c = 0; c < 3; c++) {
                const float* p = img + c * HW + nrow * W;
                m[c][0]  = m[c][1];  m[c][1]  = m[c][2];
                m[c][2]  = *reinterpret_cast<const float4*>(p + w0);
                lv[c][0] = lv[c][1]; lv[c][1] = lv[c][2];
                lv[c][2] = isL ? p[wl] : 0.f;
                rv[c][0] = rv[c][1]; rv[c][1] = rv[c][2];
                rv[c][2] = isR ? p[wr] : 0.f;
            }
        }
    }
}

extern "C" void kernel_launch(void* const* d_in, const int* in_sizes, int n_in,
                              void* d_out, int out_size)
{
    const float* img = (const float*)d_in[0];   // [1,3,1024,1024]
    const float* ker = (const float*)d_in[1];   // [9,1024,1024]
    float* out = (float*)d_out;                 // [1,3,1024,1024]

    // 2 width-halves x 256 row-groups = 512 CTAs of 128 threads.
    reblur_kernel<<<512, 128>>>(img, ker, out);
}